// round 1
// baseline (speedup 1.0000x reference)
#include <cuda_runtime.h>
#include <cstdint>

// GatedBlockParity: N x 2048 fp32 in -> N x 1664 fp32 out
// in row:  [0,256) scalars | [256,640) gates (384) | [640,1408) ns1 (256x3) | [1408,2048) ns2 (128x5)
// out row: [0,256) relu(scalars) | [256,1024) ns1*sig(g1) | [1024,1664) ns2*sig(g2)

static constexpr int IN_W   = 2048;
static constexpr int OUT_W  = 1664;
static constexpr int OUT_W4 = OUT_W / 4;   // 416 float4 per row = 13 warps exactly

__device__ __forceinline__ float sigmoidf_(float x) {
    return 1.0f / (1.0f + __expf(-x));
}

__global__ __launch_bounds__(256) void gbp_kernel(const float* __restrict__ in,
                                                  float* __restrict__ out,
                                                  int total4) {
    int idx = blockIdx.x * blockDim.x + threadIdx.x;
    if (idx >= total4) return;

    int row = idx / OUT_W4;
    int c4  = idx - row * OUT_W4;
    int c   = c4 << 2;

    const float* __restrict__ irow = in + (size_t)row * IN_W;
    float4 v;

    if (c < 256) {
        // scalars: relu
        v = *reinterpret_cast<const float4*>(irow + c);
        v.x = fmaxf(v.x, 0.0f);
        v.y = fmaxf(v.y, 0.0f);
        v.z = fmaxf(v.z, 0.0f);
        v.w = fmaxf(v.w, 0.0f);
    } else if (c < 1024) {
        // ns1: 256 groups of 3, gated by g1 = gates[0:256)
        int j = c - 256;
        v = *reinterpret_cast<const float4*>(irow + 640 + j);
        const float* __restrict__ g = irow + 256;
        v.x *= sigmoidf_(g[(j    ) / 3]);
        v.y *= sigmoidf_(g[(j + 1) / 3]);
        v.z *= sigmoidf_(g[(j + 2) / 3]);
        v.w *= sigmoidf_(g[(j + 3) / 3]);
    } else {
        // ns2: 128 groups of 5, gated by g2 = gates[256:384)
        int j = c - 1024;
        v = *reinterpret_cast<const float4*>(irow + 1408 + j);
        const float* __restrict__ g = irow + 512;
        v.x *= sigmoidf_(g[(j    ) / 5]);
        v.y *= sigmoidf_(g[(j + 1) / 5]);
        v.z *= sigmoidf_(g[(j + 2) / 5]);
        v.w *= sigmoidf_(g[(j + 3) / 5]);
    }

    *reinterpret_cast<float4*>(out + (size_t)row * OUT_W + c) = v;
}

extern "C" void kernel_launch(void* const* d_in, const int* in_sizes, int n_in,
                              void* d_out, int out_size) {
    const float* in = (const float*)d_in[0];
    float* out = (float*)d_out;

    int n_rows = in_sizes[0] / IN_W;
    int total4 = n_rows * OUT_W4;

    int threads = 256;
    int blocks = (total4 + threads - 1) / threads;
    gbp_kernel<<<blocks, threads>>>(in, out, total4);
}

// round 5
// speedup vs baseline: 1.1003x; 1.1003x over previous
#include <cuda_runtime.h>
#include <cstdint>

// GatedBlockParity: N x 2048 fp32 in -> N x 1664 fp32 out
// in row:  [0,256) scalars | [256,640) gates (384) | [640,1408) ns1 (256x3) | [1408,2048) ns2 (128x5)
// out row: [0,256) relu(scalars) | [256,1024) ns1*sig(g1) | [1024,1664) ns2*sig(g2)

static constexpr int IN_W   = 2048;
static constexpr int OUT_W  = 1664;
static constexpr int OUT_W4 = OUT_W / 4;   // 416 float4 per row = 13 warps exactly

__device__ __forceinline__ float sigmoidf_(float x) {
    return 1.0f / (1.0f + __expf(-x));
}

// Each thread processes the SAME column-float4 in two rows: row and row+rowsHalf.
// Branch condition depends only on c -> identical for both elements (no extra
// divergence), and the two LDG.128s issue back-to-back (MLP=2).
// Within one float4 of a period-p gated block, the 4 lanes touch exactly <=2
// distinct gates (i0=j/p, i0+1): load 2 gates, 2 sigmoids, select by r=j%p.
__global__ __launch_bounds__(256) void gbp_kernel(const float* __restrict__ in,
                                                  float* __restrict__ out,
                                                  int half4, int rowsHalf) {
    int idx = blockIdx.x * blockDim.x + threadIdx.x;
    if (idx >= half4) return;

    int row = idx / OUT_W4;
    int c4  = idx - row * OUT_W4;
    int c   = c4 << 2;

    const float* __restrict__ iA = in + (size_t)row * IN_W;
    const float* __restrict__ iB = iA + (size_t)rowsHalf * IN_W;
    float* __restrict__ oA = out + (size_t)row * OUT_W + c;
    float* __restrict__ oB = oA + (size_t)rowsHalf * OUT_W;

    float4 a, b;

    if (c < 256) {
        // scalars: relu
        a = *reinterpret_cast<const float4*>(iA + c);
        b = *reinterpret_cast<const float4*>(iB + c);
        a.x = fmaxf(a.x, 0.0f); a.y = fmaxf(a.y, 0.0f);
        a.z = fmaxf(a.z, 0.0f); a.w = fmaxf(a.w, 0.0f);
        b.x = fmaxf(b.x, 0.0f); b.y = fmaxf(b.y, 0.0f);
        b.z = fmaxf(b.z, 0.0f); b.w = fmaxf(b.w, 0.0f);
    } else if (c < 1024) {
        // ns1: 256 groups of 3, gated by g1 = in-row[256 + i]
        int j  = c - 256;
        a = *reinterpret_cast<const float4*>(iA + 640 + j);
        b = *reinterpret_cast<const float4*>(iB + 640 + j);
        int i0 = j / 3;
        int r  = j - 3 * i0;
        float sa0 = sigmoidf_(iA[256 + i0]);
        float sa1 = sigmoidf_(iA[256 + i0 + 1]);
        float sb0 = sigmoidf_(iB[256 + i0]);
        float sb1 = sigmoidf_(iB[256 + i0 + 1]);
        // lane gate idx: x->i0; y->i0+(r==2); z->i0+(r>=1); w->i0+1
        a.x *= sa0;                      b.x *= sb0;
        a.y *= (r == 2) ? sa1 : sa0;     b.y *= (r == 2) ? sb1 : sb0;
        a.z *= (r >= 1) ? sa1 : sa0;     b.z *= (r >= 1) ? sb1 : sb0;
        a.w *= sa1;                      b.w *= sb1;
    } else {
        // ns2: 128 groups of 5, gated by g2 = in-row[512 + i]
        int j  = c - 1024;
        a = *reinterpret_cast<const float4*>(iA + 1408 + j);
        b = *reinterpret_cast<const float4*>(iB + 1408 + j);
        int i0 = j / 5;
        int r  = j - 5 * i0;
        float sa0 = sigmoidf_(iA[512 + i0]);
        float sa1 = sigmoidf_(iA[512 + i0 + 1]);   // at i0=127 this reads ns1[0]; provably unused (r<2)
        float sb0 = sigmoidf_(iB[512 + i0]);
        float sb1 = sigmoidf_(iB[512 + i0 + 1]);
        // lane gate idx: x->i0; y->i0+(r==4); z->i0+(r>=3); w->i0+(r>=2)
        a.x *= sa0;                      b.x *= sb0;
        a.y *= (r == 4) ? sa1 : sa0;     b.y *= (r == 4) ? sb1 : sb0;
        a.z *= (r >= 3) ? sa1 : sa0;     b.z *= (r >= 3) ? sb1 : sb0;
        a.w *= (r >= 2) ? sa1 : sa0;     b.w *= (r >= 2) ? sb1 : sb0;
    }

    *reinterpret_cast<float4*>(oA) = a;
    *reinterpret_cast<float4*>(oB) = b;
}

extern "C" void kernel_launch(void* const* d_in, const int* in_sizes, int n_in,
                              void* d_out, int out_size) {
    const float* in = (const float*)d_in[0];
    float* out = (float*)d_out;

    int n_rows   = in_sizes[0] / IN_W;      // 65536 (even)
    int rowsHalf = n_rows / 2;
    int half4    = rowsHalf * OUT_W4;

    int threads = 256;
    int blocks = (half4 + threads - 1) / threads;
    gbp_kernel<<<blocks, threads>>>(in, out, half4, rowsHalf);
}